// round 4
// baseline (speedup 1.0000x reference)
#include <cuda_runtime.h>
#include <math.h>

#define N 256            // 2B
#define BH 128           // B
#define D 768
#define EPSF 1e-8f
#define INV_TEMP 20.0f   // 1/0.05

// ---------------- scratch (device globals; no allocation) ----------------
__device__ float g_Gs[N * N];
__device__ float g_Gt[N * N];
__device__ float g_ds[N * N];
__device__ float g_dt[N * N];
__device__ float g_rs[N * N];   // 1/(||xi-xj||+eps), DIAGONAL ZEROED
__device__ float g_rt[N * N];
__device__ float g_pds[N];      // per-block triu partial sums of ds
__device__ float g_pdt[N];      // per-block triu partial sums of dt
__device__ float g_pdist[N];    // per-block distance-huber partials
__device__ float g_pang[N];     // per-block angle-huber partials
__device__ float g_means[2];    // mean_sd, mean_td

// ---------------- helpers ----------------
__device__ __forceinline__ const float* row_ptr(const float* q, const float* p, int r) {
    return (r < BH) ? (q + r * D) : (p + (r - BH) * D);
}

// branchless huber: a=|d|, m=min(a,1) -> 0.5*m*(2a-m)
// a<1: 0.5*a*a ; a>=1: 0.5*(2a-1)=a-0.5
__device__ __forceinline__ float huber(float d) {
    float a = fabsf(d);
    float m = fminf(a, 1.0f);
    return 0.5f * m * (2.0f * a - m);
}

// block-wide sum; blockDim.x <= 256, multiple of 32. Result valid on thread 0.
__device__ __forceinline__ float block_sum(float v) {
    __shared__ float sbuf[8];
    #pragma unroll
    for (int o = 16; o > 0; o >>= 1) v += __shfl_down_sync(0xffffffffu, v, o);
    int w = threadIdx.x >> 5, l = threadIdx.x & 31;
    if (l == 0) sbuf[w] = v;
    __syncthreads();
    float s = 0.0f;
    if (threadIdx.x == 0) {
        int nw = blockDim.x >> 5;
        for (int i = 0; i < nw; i++) s += sbuf[i];
    }
    return s;
}

// ---------------- K1: Gram matrices G = X X^T ----------------
// grid (8,8,2), block (16,16); z=0 -> student, z=1 -> teacher
__global__ void gram_kernel(const float* __restrict__ sq, const float* __restrict__ sp,
                            const float* __restrict__ tq, const float* __restrict__ tp) {
    const float* q = blockIdx.z ? tq : sq;
    const float* p = blockIdx.z ? tp : sp;
    float* G = blockIdx.z ? g_Gt : g_Gs;

    __shared__ float As[32][33];
    __shared__ float Bs[32][33];

    int TI = blockIdx.x * 32;
    int TK = blockIdx.y * 32;
    int tx = threadIdx.x, ty = threadIdx.y;
    int tid = ty * 16 + tx;

    float acc00 = 0.f, acc01 = 0.f, acc10 = 0.f, acc11 = 0.f;

    for (int k0 = 0; k0 < D; k0 += 32) {
        #pragma unroll
        for (int l = 0; l < 4; l++) {
            int idx = tid + l * 256;
            int r = idx >> 5, c = idx & 31;
            As[r][c] = row_ptr(q, p, TI + r)[k0 + c];
            Bs[r][c] = row_ptr(q, p, TK + r)[k0 + c];
        }
        __syncthreads();
        #pragma unroll
        for (int kk = 0; kk < 32; kk++) {
            float a0 = As[ty][kk],      a1 = As[ty + 16][kk];
            float b0 = Bs[tx][kk],      b1 = Bs[tx + 16][kk];
            acc00 += a0 * b0; acc01 += a0 * b1;
            acc10 += a1 * b0; acc11 += a1 * b1;
        }
        __syncthreads();
    }
    G[(TI + ty)      * N + TK + tx]      = acc00;
    G[(TI + ty)      * N + TK + tx + 16] = acc01;
    G[(TI + ty + 16) * N + TK + tx]      = acc10;
    G[(TI + ty + 16) * N + TK + tx + 16] = acc11;
}

// ---------------- K2: distances, inverse norms (diag zeroed), triu partials ----------------
// grid 256 (row i), block 256 (col j)
__global__ void dist_prep_kernel() {
    int i = blockIdx.x, j = threadIdx.x;
    float gij_s = g_Gs[i * N + j];
    float gii_s = g_Gs[i * N + i];
    float gjj_s = g_Gs[j * N + j];
    float ds = gii_s + gjj_s - 2.0f * gij_s;
    g_ds[i * N + j] = ds;
    // Zero the diagonal of r: makes i==j angle terms contribute exactly 0
    g_rs[i * N + j] = (i == j) ? 0.0f : 1.0f / (sqrtf(fmaxf(ds, 0.0f)) + EPSF);

    float gij_t = g_Gt[i * N + j];
    float gii_t = g_Gt[i * N + i];
    float gjj_t = g_Gt[j * N + j];
    float dt = gii_t + gjj_t - 2.0f * gij_t;
    g_dt[i * N + j] = dt;
    g_rt[i * N + j] = (i == j) ? 0.0f : 1.0f / (sqrtf(fmaxf(dt, 0.0f)) + EPSF);

    float cds = (j > i) ? ds : 0.0f;
    float cdt = (j > i) ? dt : 0.0f;
    float s1 = block_sum(cds);
    if (threadIdx.x == 0) g_pds[i] = s1;
    __syncthreads();
    float s2 = block_sum(cdt);
    if (threadIdx.x == 0) g_pdt[i] = s2;
}

// ---------------- K2b: means ----------------
__global__ void mean_kernel() {
    int t = threadIdx.x;  // 256 threads
    float s1 = block_sum(g_pds[t]);
    if (t == 0) g_means[0] = s1 / 32640.0f + EPSF;
    __syncthreads();
    float s2 = block_sum(g_pdt[t]);
    if (t == 0) g_means[1] = s2 / 32640.0f + EPSF;
}

// ---------------- K3: distance huber partials ----------------
// grid 256 (row i), block 256 (col j)
__global__ void dist_loss_kernel() {
    int i = blockIdx.x, j = threadIdx.x;
    float inv_msd = 1.0f / g_means[0];
    float inv_mtd = 1.0f / g_means[1];
    float v = 0.0f;
    if (j > i) {
        float diff = g_ds[i * N + j] * inv_msd - g_dt[i * N + j] * inv_mtd;
        v = huber(diff);
    }
    float s = block_sum(v);
    if (threadIdx.x == 0) g_pdist[i] = s;
}

// ---------------- K4: angle huber partials ----------------
// grid 256 (j), block 256 (thread handles k = tid, loops over i)
// cos_s(i,k at vertex j) = r_k * ( r_i*(g_ik - g_jk) + p_i ),  p_i = (g_jj - g_ji)*r_i
// With r diagonal zeroed: i==j gives 0; k==j gives 0. Only i==k needs masking.
__global__ void angle_kernel() {
    int j = blockIdx.x, k = threadIdx.x;
    __shared__ float rs_sh[N], rt_sh[N], ps_sh[N], pt_sh[N], gsj_sh[N], gtj_sh[N];
    {
        float gjk_s = g_Gs[j * N + k];
        float gjk_t = g_Gt[j * N + k];
        float rk_s  = g_rs[j * N + k];
        float rk_t  = g_rt[j * N + k];
        gsj_sh[k] = gjk_s;
        gtj_sh[k] = gjk_t;
        rs_sh[k] = rk_s;
        rt_sh[k] = rk_t;
        // p_k relative to row j: (g_jj - g_jk) * r_jk ; needs g_jj
    }
    __syncthreads();
    {
        float gjj_s = gsj_sh[j];
        float gjj_t = gtj_sh[j];
        ps_sh[k] = (gjj_s - gsj_sh[k]) * rs_sh[k];
        pt_sh[k] = (gjj_t - gtj_sh[k]) * rt_sh[k];
    }
    __syncthreads();

    float rsk = rs_sh[k], rtk = rt_sh[k];
    float gs_jk = gsj_sh[k], gt_jk = gtj_sh[k];
    const float* __restrict__ Gsk = g_Gs + k;  // column k (row-major stride N)
    const float* __restrict__ Gtk = g_Gt + k;

    float acc = 0.0f;
    #pragma unroll 4
    for (int i = 0; i < N; i++) {
        float us = fmaf(rs_sh[i], Gsk[i * N] - gs_jk, ps_sh[i]);
        float ut = fmaf(rt_sh[i], Gtk[i * N] - gt_jk, pt_sh[i]);
        float d  = fmaf(rtk, -ut, rsk * us);   // cos_s - cos_t
        float a  = fabsf(d);
        float m  = fminf(a, 1.0f);
        float h  = m * (2.0f * a - m);         // 2*huber
        acc += (i != k) ? h : 0.0f;
    }
    acc *= 0.5f;

    float s = block_sum(acc);
    if (threadIdx.x == 0) g_pang[j] = s;
}

// ---------------- K5: contrastive + combine ----------------
// 1 block, 128 threads (one per query row)
__global__ void final_kernel(float* __restrict__ out, int out_size) {
    int t = threadIdx.x;

    // contrastive: scores[t, c] = G_s[t, 128 + c] * 20
    const float* row = g_Gs + t * N + BH;
    float mx = -INFINITY;
    #pragma unroll 4
    for (int c = 0; c < BH; c++) mx = fmaxf(mx, row[c]);
    float sum = 0.0f;
    #pragma unroll 4
    for (int c = 0; c < BH; c++) sum += expf(INV_TEMP * (row[c] - mx));
    float logZ = INV_TEMP * mx + logf(sum);
    float cl = logZ - INV_TEMP * row[t];

    float clsum = block_sum(cl);
    __syncthreads();
    float dsum = block_sum(g_pdist[t] + g_pdist[t + BH]);
    __syncthreads();
    float asum = block_sum(g_pang[t] + g_pang[t + BH]);

    if (t == 0) {
        float contrastive = clsum / (float)BH;
        float dist_loss = dsum / 32640.0f;                 // n(n-1)/2
        float ang_loss  = asum / 16581120.0f;              // n(n-1)(n-2)
        float kd = 0.5f * dist_loss + 0.5f * ang_loss;
        float total = contrastive + kd;
        if (out_size > 0) out[0] = total;
        if (out_size > 1) out[1] = contrastive;
        if (out_size > 2) out[2] = kd;
    }
}

// ---------------- launch ----------------
extern "C" void kernel_launch(void* const* d_in, const int* in_sizes, int n_in,
                              void* d_out, int out_size) {
    const float* sq = (const float*)d_in[0];
    const float* sp = (const float*)d_in[1];
    const float* tq = (const float*)d_in[2];
    const float* tp = (const float*)d_in[3];
    float* out = (float*)d_out;

    dim3 ggrid(8, 8, 2), gblk(16, 16);
    gram_kernel<<<ggrid, gblk>>>(sq, sp, tq, tp);
    dist_prep_kernel<<<N, N>>>();
    mean_kernel<<<1, N>>>();
    dist_loss_kernel<<<N, N>>>();
    angle_kernel<<<N, N>>>();
    final_kernel<<<1, BH>>>(out, out_size);
}

// round 7
// speedup vs baseline: 1.2628x; 1.2628x over previous
#include <cuda_runtime.h>
#include <math.h>

#define N 256            // 2B
#define BH 128           // B
#define D 768
#define EPSF 1e-8f
#define INV_TEMP 20.0f   // 1/0.05
#define CNT2 32640.0f    // N(N-1)/2
#define CNT3 16581120.0f // N(N-1)(N-2)

// ---------------- scratch (device globals; no allocation) ----------------
__device__ float g_Gs[N * N];
__device__ float g_Gt[N * N];
__device__ float g_n2s[N];       // diag of Gs (row squared norms)
__device__ float g_n2t[N];
__device__ float g_psum[2][64];  // per-gram-block tile sums (z, bx*8+by)
__device__ float g_pang[N];      // per-block angle partials (sum of huber, i!=k, vertex j)
__device__ float g_pdist[N];     // per-block distance-huber partials (row j, k>j)
__device__ float g_pcl[BH];      // per-row contrastive loss

// ---------------- helpers ----------------
__device__ __forceinline__ const float* row_ptr(const float* q, const float* p, int r) {
    return (r < BH) ? (q + r * D) : (p + (r - BH) * D);
}

// Generic block-wide sum with EXPLICIT linear tid and thread count.
// Works for any block shape; result broadcast to all threads.
__device__ __forceinline__ float block_sum_tid(float v, int tid, int nthreads) {
    __shared__ float sbuf[9];
    __syncthreads();                       // protect sbuf reuse across calls
    #pragma unroll
    for (int o = 16; o > 0; o >>= 1) v += __shfl_down_sync(0xffffffffu, v, o);
    int w = tid >> 5, l = tid & 31;
    if (l == 0) sbuf[w] = v;
    __syncthreads();
    if (tid == 0) {
        float s = 0.0f;
        int nw = nthreads >> 5;
        for (int i = 0; i < nw; i++) s += sbuf[i];
        sbuf[8] = s;
    }
    __syncthreads();
    return sbuf[8];
}

__device__ __forceinline__ float block_sum_all(float v) {
    return block_sum_tid(v, threadIdx.x, blockDim.x);
}

// block-wide max, result broadcast to ALL threads (1-D blocks only).
__device__ __forceinline__ float block_max_all(float v) {
    __shared__ float mbuf[9];
    __syncthreads();
    #pragma unroll
    for (int o = 16; o > 0; o >>= 1) v = fmaxf(v, __shfl_down_sync(0xffffffffu, v, o));
    int w = threadIdx.x >> 5, l = threadIdx.x & 31;
    if (l == 0) mbuf[w] = v;
    __syncthreads();
    if (threadIdx.x == 0) {
        float s = -INFINITY;
        int nw = blockDim.x >> 5;
        for (int i = 0; i < nw; i++) s = fmaxf(s, mbuf[i]);
        mbuf[8] = s;
    }
    __syncthreads();
    return mbuf[8];
}

// ---------------- K1: Gram matrices G = X X^T, + diag (n2) + tile-sum partials ----------------
// grid (8,8,2), block (16,16); z=0 -> student, z=1 -> teacher
__global__ void gram_kernel(const float* __restrict__ sq, const float* __restrict__ sp,
                            const float* __restrict__ tq, const float* __restrict__ tp) {
    const float* q = blockIdx.z ? tq : sq;
    const float* p = blockIdx.z ? tp : sp;
    float* G  = blockIdx.z ? g_Gt  : g_Gs;
    float* n2 = blockIdx.z ? g_n2t : g_n2s;

    __shared__ float As[32][33];
    __shared__ float Bs[32][33];

    int TI = blockIdx.x * 32;
    int TK = blockIdx.y * 32;
    int tx = threadIdx.x, ty = threadIdx.y;
    int tid = ty * 16 + tx;

    float acc00 = 0.f, acc01 = 0.f, acc10 = 0.f, acc11 = 0.f;

    for (int k0 = 0; k0 < D; k0 += 32) {
        #pragma unroll
        for (int l = 0; l < 4; l++) {
            int idx = tid + l * 256;
            int r = idx >> 5, c = idx & 31;
            As[r][c] = row_ptr(q, p, TI + r)[k0 + c];
            Bs[r][c] = row_ptr(q, p, TK + r)[k0 + c];
        }
        __syncthreads();
        #pragma unroll
        for (int kk = 0; kk < 32; kk++) {
            float a0 = As[ty][kk],      a1 = As[ty + 16][kk];
            float b0 = Bs[tx][kk],      b1 = Bs[tx + 16][kk];
            acc00 += a0 * b0; acc01 += a0 * b1;
            acc10 += a1 * b0; acc11 += a1 * b1;
        }
        __syncthreads();
    }
    G[(TI + ty)      * N + TK + tx]      = acc00;
    G[(TI + ty)      * N + TK + tx + 16] = acc01;
    G[(TI + ty + 16) * N + TK + tx]      = acc10;
    G[(TI + ty + 16) * N + TK + tx + 16] = acc11;

    // diagonal (squared norms) from diagonal tiles
    if (blockIdx.x == blockIdx.y && tx == ty) {
        n2[TI + ty]      = acc00;   // row TI+ty,    col TK+tx    == same index
        n2[TI + ty + 16] = acc11;   // row TI+ty+16, col TK+tx+16 == same index
    }

    // per-block tile sum (for sum(G) -> analytic triu-distance mean)
    // NOTE: tid-explicit reduction — this block is 2-D (16,16)!
    float s = block_sum_tid(acc00 + acc01 + acc10 + acc11, tid, 256);
    if (tid == 0) g_psum[blockIdx.z][blockIdx.x * 8 + blockIdx.y] = s;
}

// ---------------- K2: fused angle + distance-huber + contrastive rows ----------------
// grid 256 (j), block 256 (k = tid)
// cos_s(i,k vertex j) = r_jk * ( r_ji*(g_ik - g_jk) + p_i ),  p_i = (g_jj - g_ji)*r_ji
// r row-j diagonal zeroed => i==j and k==j terms contribute exactly 0; (i,k) symmetric
// so only i>k is summed (per-warp uniform loop base keeps loads coalesced).
__global__ void fused_kernel() {
    int j = blockIdx.x, k = threadIdx.x;
    __shared__ float n2s_sh[N], n2t_sh[N];
    __shared__ float gsj_sh[N], gtj_sh[N];
    __shared__ float rs_sh[N],  rt_sh[N];
    __shared__ float ps_sh[N],  pt_sh[N];

    float n2sk = g_n2s[k];
    float n2tk = g_n2t[k];
    n2s_sh[k] = n2sk;
    n2t_sh[k] = n2tk;
    float gs = g_Gs[j * N + k];
    float gt = g_Gt[j * N + k];
    gsj_sh[k] = gs;
    gtj_sh[k] = gt;
    __syncthreads();

    float n2sj = n2s_sh[j], n2tj = n2t_sh[j];
    float ds_jk = n2sj + n2sk - 2.0f * gs;
    float dt_jk = n2tj + n2tk - 2.0f * gt;
    float rs = (k == j) ? 0.0f : 1.0f / (sqrtf(fmaxf(ds_jk, 0.0f)) + EPSF);
    float rt = (k == j) ? 0.0f : 1.0f / (sqrtf(fmaxf(dt_jk, 0.0f)) + EPSF);
    rs_sh[k] = rs;
    rt_sh[k] = rt;
    ps_sh[k] = (n2sj - gs) * rs;
    pt_sh[k] = (n2tj - gt) * rt;

    // ---- means (analytic): triu ds sum = N*tr(G) - sum(G) ----
    float tr_s = block_sum_all(n2sk);
    float tr_t = block_sum_all(n2tk);
    float sumG_s = block_sum_all((k < 64) ? g_psum[0][k] : 0.0f);
    float sumG_t = block_sum_all((k < 64) ? g_psum[1][k] : 0.0f);
    float inv_ms = 1.0f / (((float)N * tr_s - sumG_s) / CNT2 + EPSF);
    float inv_mt = 1.0f / (((float)N * tr_t - sumG_t) / CNT2 + EPSF);

    // ---- distance huber, row j, cols k>j (all operands already local) ----
    {
        float v = 0.0f;
        if (k > j) {
            float diff = ds_jk * inv_ms - dt_jk * inv_mt;
            float a = fabsf(diff);
            float m = fminf(a, 1.0f);
            v = 0.5f * m * (2.0f * a - m);
        }
        float s = block_sum_all(v);
        if (k == 0) g_pdist[j] = s;
    }

    // ---- contrastive, row j (only j < BH): scores = Gs[j, BH+c]*20 ----
    if (j < BH) {
        float sval = (k < BH) ? gsj_sh[BH + k] : -INFINITY;
        float mx = block_max_all(sval);
        float ex = (k < BH) ? expf(INV_TEMP * (sval - mx)) : 0.0f;
        float sm = block_sum_all(ex);
        if (k == 0)
            g_pcl[j] = INV_TEMP * mx + logf(sm) - INV_TEMP * gsj_sh[BH + j];
    }

    // ---- angle loop: i > k only (pair symmetry), warp-uniform base for coalescing ----
    float rsk = rs, rtk = rt;
    float gs_jk = gs, gt_jk = gt;
    const float* __restrict__ Gsk = g_Gs + k;   // column k (stride N)
    const float* __restrict__ Gtk = g_Gt + k;

    int wbase = k & ~31;
    float acc = 0.0f;
    #pragma unroll 4
    for (int i = wbase + 1; i < N; i++) {
        float us = fmaf(rs_sh[i], Gsk[i * N] - gs_jk, ps_sh[i]);
        float ut = fmaf(rt_sh[i], Gtk[i * N] - gt_jk, pt_sh[i]);
        float d  = fmaf(rtk, -ut, rsk * us);    // cos_s - cos_t
        float a  = fabsf(d);
        float m  = fminf(a, 1.0f);
        float h  = m * (2.0f * a - m);          // 2*huber
        acc += (i > k) ? h : 0.0f;
    }
    // sum_{i>k} 2*huber == sum_{i!=k} huber
    float s = block_sum_all(acc);
    if (k == 0) g_pang[j] = s;
}

// ---------------- K3: final reduction + combine ----------------
__global__ void final_kernel(float* __restrict__ out, int out_size) {
    int t = threadIdx.x;  // 256
    float dsum  = block_sum_all(g_pdist[t]);
    float asum  = block_sum_all(g_pang[t]);
    float clsum = block_sum_all((t < BH) ? g_pcl[t] : 0.0f);

    if (t == 0) {
        float contrastive = clsum / (float)BH;
        float dist_loss = dsum / CNT2;
        float ang_loss  = asum / CNT3;
        float kd = 0.5f * dist_loss + 0.5f * ang_loss;
        float total = contrastive + kd;
        if (out_size > 0) out[0] = total;
        if (out_size > 1) out[1] = contrastive;
        if (out_size > 2) out[2] = kd;
    }
}

// ---------------- launch ----------------
extern "C" void kernel_launch(void* const* d_in, const int* in_sizes, int n_in,
                              void* d_out, int out_size) {
    const float* sq = (const float*)d_in[0];
    const float* sp = (const float*)d_in[1];
    const float* tq = (const float*)d_in[2];
    const float* tp = (const float*)d_in[3];
    float* out = (float*)d_out;

    dim3 ggrid(8, 8, 2), gblk(16, 16);
    gram_kernel<<<ggrid, gblk>>>(sq, sp, tq, tp);
    fused_kernel<<<N, N>>>();
    final_kernel<<<1, N>>>(out, out_size);
}

// round 8
// speedup vs baseline: 1.5073x; 1.1936x over previous
#include <cuda_runtime.h>
#include <math.h>

#define N 256            // 2B
#define BH 128           // B
#define D 768
#define EPSF 1e-8f
#define INV_TEMP 20.0f   // 1/0.05
#define CNT2 32640.0f    // N(N-1)/2
#define CNT3 16581120.0f // N(N-1)(N-2)

#define SPLITK 8
#define CHUNK 96         // D / SPLITK
#define TSTEP 16         // k per smem stage

// ---------------- scratch (device globals; no allocation) ----------------
__device__ float g_Gp[2][SPLITK][N * N];  // split-K partials (4 MB)
__device__ float g_Gs[N * N];
__device__ float g_Gt[N * N];
__device__ float g_n2s[N];       // diag of Gs (row squared norms)
__device__ float g_n2t[N];
__device__ float g_rowsum[2][N]; // per-row sums of G (for analytic means)
__device__ float g_pang[N];      // per-block angle partials
__device__ float g_pdist[N];     // per-block distance-huber partials
__device__ float g_pcl[BH];      // per-row contrastive loss

// ---------------- helpers ----------------
__device__ __forceinline__ const float* row_ptr(const float* q, const float* p, int r) {
    return (r < BH) ? (q + r * D) : (p + (r - BH) * D);
}

// block-wide sum, EXPLICIT linear tid/count; result broadcast to all threads.
__device__ __forceinline__ float block_sum_tid(float v, int tid, int nthreads) {
    __shared__ float sbuf[9];
    __syncthreads();                       // protect sbuf reuse across calls
    #pragma unroll
    for (int o = 16; o > 0; o >>= 1) v += __shfl_down_sync(0xffffffffu, v, o);
    int w = tid >> 5, l = tid & 31;
    if (l == 0) sbuf[w] = v;
    __syncthreads();
    if (tid == 0) {
        float s = 0.0f;
        int nw = nthreads >> 5;
        for (int i = 0; i < nw; i++) s += sbuf[i];
        sbuf[8] = s;
    }
    __syncthreads();
    return sbuf[8];
}

__device__ __forceinline__ float block_sum_all(float v) {
    return block_sum_tid(v, threadIdx.x, blockDim.x);
}

// block-wide max, result broadcast (1-D blocks only).
__device__ __forceinline__ float block_max_all(float v) {
    __shared__ float mbuf[9];
    __syncthreads();
    #pragma unroll
    for (int o = 16; o > 0; o >>= 1) v = fmaxf(v, __shfl_down_sync(0xffffffffu, v, o));
    int w = threadIdx.x >> 5, l = threadIdx.x & 31;
    if (l == 0) mbuf[w] = v;
    __syncthreads();
    if (threadIdx.x == 0) {
        float s = -INFINITY;
        int nw = blockDim.x >> 5;
        for (int i = 0; i < nw; i++) s = fmaxf(s, mbuf[i]);
        mbuf[8] = s;
    }
    __syncthreads();
    return mbuf[8];
}

// ---------------- K1: split-K Gram partials ----------------
// grid (4,4,16): x,y = 64x64 tile; z = mat*8 + split. block = 256 threads.
// Each thread computes a 4x4 register tile; smem staged k-major so the inner
// loop is 2x LDS.128 + 16 FFMA per k.
__global__ void gram_kernel(const float* __restrict__ sq, const float* __restrict__ sp,
                            const float* __restrict__ tq, const float* __restrict__ tp) {
    int mat = blockIdx.z >> 3;
    int split = blockIdx.z & 7;
    const float* q = mat ? tq : sq;
    const float* p = mat ? tp : sp;
    float* Gp = g_Gp[mat][split];

    __shared__ float As[TSTEP][68];   // k-major, stride 68 (16B-aligned rows)
    __shared__ float Bs[TSTEP][68];

    int TI = blockIdx.x * 64;
    int TK = blockIdx.y * 64;
    int tid = threadIdx.x;
    int tx = tid & 15, ty = tid >> 4;

    // load mapping: r = tid/4 (0..63), c4 = (tid%4)*4 -> one float4 each for A,B
    int lr = tid >> 2;
    int lc = (tid & 3) * 4;

    float acc[4][4];
    #pragma unroll
    for (int a = 0; a < 4; a++)
        #pragma unroll
        for (int b = 0; b < 4; b++) acc[a][b] = 0.0f;

    int k0base = split * CHUNK;
    #pragma unroll 1
    for (int s = 0; s < CHUNK / TSTEP; s++) {
        int k0 = k0base + s * TSTEP;
        float4 av = *(const float4*)(row_ptr(q, p, TI + lr) + k0 + lc);
        float4 bv = *(const float4*)(row_ptr(q, p, TK + lr) + k0 + lc);
        As[lc + 0][lr] = av.x; As[lc + 1][lr] = av.y;
        As[lc + 2][lr] = av.z; As[lc + 3][lr] = av.w;
        Bs[lc + 0][lr] = bv.x; Bs[lc + 1][lr] = bv.y;
        Bs[lc + 2][lr] = bv.z; Bs[lc + 3][lr] = bv.w;
        __syncthreads();
        #pragma unroll
        for (int kk = 0; kk < TSTEP; kk++) {
            float4 a = *(const float4*)&As[kk][ty * 4];
            float4 b = *(const float4*)&Bs[kk][tx * 4];
            acc[0][0] = fmaf(a.x, b.x, acc[0][0]);
            acc[0][1] = fmaf(a.x, b.y, acc[0][1]);
            acc[0][2] = fmaf(a.x, b.z, acc[0][2]);
            acc[0][3] = fmaf(a.x, b.w, acc[0][3]);
            acc[1][0] = fmaf(a.y, b.x, acc[1][0]);
            acc[1][1] = fmaf(a.y, b.y, acc[1][1]);
            acc[1][2] = fmaf(a.y, b.z, acc[1][2]);
            acc[1][3] = fmaf(a.y, b.w, acc[1][3]);
            acc[2][0] = fmaf(a.z, b.x, acc[2][0]);
            acc[2][1] = fmaf(a.z, b.y, acc[2][1]);
            acc[2][2] = fmaf(a.z, b.z, acc[2][2]);
            acc[2][3] = fmaf(a.z, b.w, acc[2][3]);
            acc[3][0] = fmaf(a.w, b.x, acc[3][0]);
            acc[3][1] = fmaf(a.w, b.y, acc[3][1]);
            acc[3][2] = fmaf(a.w, b.z, acc[3][2]);
            acc[3][3] = fmaf(a.w, b.w, acc[3][3]);
        }
        __syncthreads();
    }

    #pragma unroll
    for (int r = 0; r < 4; r++) {
        float4 v = make_float4(acc[r][0], acc[r][1], acc[r][2], acc[r][3]);
        *(float4*)&Gp[(TI + ty * 4 + r) * N + TK + tx * 4] = v;
    }
}

// ---------------- K1b: fold split-K partials, emit diag + row sums ----------------
// grid (N, 2), block 256. element [i, t] of matrix z.
__global__ void reduce_kernel() {
    int i = blockIdx.x, z = blockIdx.y, t = threadIdx.x;
    float s = 0.0f;
    #pragma unroll
    for (int pp = 0; pp < SPLITK; pp++) s += g_Gp[z][pp][i * N + t];
    (z ? g_Gt : g_Gs)[i * N + t] = s;
    if (t == i) (z ? g_n2t : g_n2s)[i] = s;
    float rsum = block_sum_all(s);
    if (t == 0) g_rowsum[z][i] = rsum;
}

// ---------------- K2: fused angle + distance-huber + contrastive rows ----------------
// grid 256 (j), block 256 (k = tid)
// cos_s(i,k vertex j) = r_jk * ( r_ji*(g_ik - g_jk) + p_i ),  p_i = (g_jj - g_ji)*r_ji
// r row-j diagonal zeroed => i==j and k==j terms contribute exactly 0; (i,k) symmetric
// so only i>k is summed (per-warp uniform loop base keeps loads coalesced).
__global__ void fused_kernel() {
    int j = blockIdx.x, k = threadIdx.x;
    __shared__ float n2s_sh[N], n2t_sh[N];
    __shared__ float gsj_sh[N], gtj_sh[N];
    __shared__ float rs_sh[N],  rt_sh[N];
    __shared__ float ps_sh[N],  pt_sh[N];

    float n2sk = g_n2s[k];
    float n2tk = g_n2t[k];
    n2s_sh[k] = n2sk;
    n2t_sh[k] = n2tk;
    float gs = g_Gs[j * N + k];
    float gt = g_Gt[j * N + k];
    gsj_sh[k] = gs;
    gtj_sh[k] = gt;
    __syncthreads();

    float n2sj = n2s_sh[j], n2tj = n2t_sh[j];
    float ds_jk = n2sj + n2sk - 2.0f * gs;
    float dt_jk = n2tj + n2tk - 2.0f * gt;
    float rs = (k == j) ? 0.0f : 1.0f / (sqrtf(fmaxf(ds_jk, 0.0f)) + EPSF);
    float rt = (k == j) ? 0.0f : 1.0f / (sqrtf(fmaxf(dt_jk, 0.0f)) + EPSF);
    rs_sh[k] = rs;
    rt_sh[k] = rt;
    ps_sh[k] = (n2sj - gs) * rs;
    pt_sh[k] = (n2tj - gt) * rt;

    // ---- means (analytic): triu ds sum = N*tr(G) - sum(G) ----
    float tr_s = block_sum_all(n2sk);
    float tr_t = block_sum_all(n2tk);
    float sumG_s = block_sum_all(g_rowsum[0][k]);
    float sumG_t = block_sum_all(g_rowsum[1][k]);
    float inv_ms = 1.0f / (((float)N * tr_s - sumG_s) / CNT2 + EPSF);
    float inv_mt = 1.0f / (((float)N * tr_t - sumG_t) / CNT2 + EPSF);

    // ---- distance huber, row j, cols k>j ----
    {
        float v = 0.0f;
        if (k > j) {
            float diff = ds_jk * inv_ms - dt_jk * inv_mt;
            float a = fabsf(diff);
            float m = fminf(a, 1.0f);
            v = 0.5f * m * (2.0f * a - m);
        }
        float s = block_sum_all(v);
        if (k == 0) g_pdist[j] = s;
    }

    // ---- contrastive, row j (only j < BH): scores = Gs[j, BH+c]*20 ----
    if (j < BH) {
        float sval = (k < BH) ? gsj_sh[BH + k] : -INFINITY;
        float mx = block_max_all(sval);
        float ex = (k < BH) ? expf(INV_TEMP * (sval - mx)) : 0.0f;
        float sm = block_sum_all(ex);
        if (k == 0)
            g_pcl[j] = INV_TEMP * mx + logf(sm) - INV_TEMP * gsj_sh[BH + j];
    }

    // ---- angle loop: i > k only (pair symmetry), warp-uniform base ----
    float rsk = rs, rtk = rt;
    float gs_jk = gs, gt_jk = gt;
    const float* __restrict__ Gsk = g_Gs + k;   // column k (stride N)
    const float* __restrict__ Gtk = g_Gt + k;

    int wbase = k & ~31;
    float acc = 0.0f;
    #pragma unroll 4
    for (int i = wbase + 1; i < N; i++) {
        float us = fmaf(rs_sh[i], Gsk[i * N] - gs_jk, ps_sh[i]);
        float ut = fmaf(rt_sh[i], Gtk[i * N] - gt_jk, pt_sh[i]);
        float d  = fmaf(rtk, -ut, rsk * us);    // cos_s - cos_t
        float a  = fabsf(d);
        float m  = fminf(a, 1.0f);
        float h  = m * (2.0f * a - m);          // 2*huber
        acc += (i > k) ? h : 0.0f;
    }
    // sum_{i>k} 2*huber == sum_{i!=k} huber
    float s = block_sum_all(acc);
    if (k == 0) g_pang[j] = s;
}

// ---------------- K3: final reduction + combine ----------------
__global__ void final_kernel(float* __restrict__ out, int out_size) {
    int t = threadIdx.x;  // 256
    float dsum  = block_sum_all(g_pdist[t]);
    float asum  = block_sum_all(g_pang[t]);
    float clsum = block_sum_all((t < BH) ? g_pcl[t] : 0.0f);

    if (t == 0) {
        float contrastive = clsum / (float)BH;
        float dist_loss = dsum / CNT2;
        float ang_loss  = asum / CNT3;
        float kd = 0.5f * dist_loss + 0.5f * ang_loss;
        float total = contrastive + kd;
        if (out_size > 0) out[0] = total;
        if (out_size > 1) out[1] = contrastive;
        if (out_size > 2) out[2] = kd;
    }
}

// ---------------- launch ----------------
extern "C" void kernel_launch(void* const* d_in, const int* in_sizes, int n_in,
                              void* d_out, int out_size) {
    const float* sq = (const float*)d_in[0];
    const float* sp = (const float*)d_in[1];
    const float* tq = (const float*)d_in[2];
    const float* tp = (const float*)d_in[3];
    float* out = (float*)d_out;

    dim3 ggrid(4, 4, 16);
    gram_kernel<<<ggrid, 256>>>(sq, sp, tq, tp);
    reduce_kernel<<<dim3(N, 2), 256>>>();
    fused_kernel<<<N, 256>>>();
    final_kernel<<<1, 256>>>(out, out_size);
}

// round 9
// speedup vs baseline: 2.8777x; 1.9093x over previous
#include <cuda_runtime.h>
#include <math.h>

#define N 256            // 2B
#define BH 128           // B
#define D 768
#define EPSF 1e-8f
#define INV_TEMP 20.0f   // 1/0.05
#define CNT2 32640.0f    // N(N-1)/2
#define CNT3 16581120.0f // N(N-1)(N-2)

#define SPLITK 8
#define CHUNK 96         // D / SPLITK
#define TSTEP 16         // k per smem stage

#define NFB 512          // fused grid: 64 j-quads x 8 i-combs

// ---------------- scratch (device globals; no allocation) ----------------
__device__ float g_Gp[2][SPLITK][N * N];  // split-K partials (4 MB)
__device__ float g_Gs[N * N];
__device__ float g_Gt[N * N];
__device__ float g_n2s[N];       // diag of Gs (row squared norms)
__device__ float g_n2t[N];
__device__ float g_rowsum[2][N]; // per-row sums of G
__device__ float g_invm[2];      // 1/mean_sd, 1/mean_td
__device__ float g_pang[NFB];    // per-fused-block angle partials
__device__ float g_pdist[N];     // per-j distance-huber partials
__device__ float g_pcl[BH];      // per-row contrastive loss
__device__ unsigned int g_ctr1 = 0;  // reduce ticket
__device__ unsigned int g_ctr2 = 0;  // fused ticket

// ---------------- helpers ----------------
__device__ __forceinline__ const float* row_ptr(const float* q, const float* p, int r) {
    return (r < BH) ? (q + r * D) : (p + (r - BH) * D);
}

// block-wide sum, EXPLICIT linear tid/count; result broadcast to all threads.
__device__ __forceinline__ float block_sum_tid(float v, int tid, int nthreads) {
    __shared__ float sbuf[9];
    __syncthreads();                       // protect sbuf reuse across calls
    #pragma unroll
    for (int o = 16; o > 0; o >>= 1) v += __shfl_down_sync(0xffffffffu, v, o);
    int w = tid >> 5, l = tid & 31;
    if (l == 0) sbuf[w] = v;
    __syncthreads();
    if (tid == 0) {
        float s = 0.0f;
        int nw = nthreads >> 5;
        for (int i = 0; i < nw; i++) s += sbuf[i];
        sbuf[8] = s;
    }
    __syncthreads();
    return sbuf[8];
}

__device__ __forceinline__ float block_sum_all(float v) {
    return block_sum_tid(v, threadIdx.x, blockDim.x);
}

// block-wide max, result broadcast (1-D blocks only).
__device__ __forceinline__ float block_max_all(float v) {
    __shared__ float mbuf[9];
    __syncthreads();
    #pragma unroll
    for (int o = 16; o > 0; o >>= 1) v = fmaxf(v, __shfl_down_sync(0xffffffffu, v, o));
    int w = threadIdx.x >> 5, l = threadIdx.x & 31;
    if (l == 0) mbuf[w] = v;
    __syncthreads();
    if (threadIdx.x == 0) {
        float s = -INFINITY;
        int nw = blockDim.x >> 5;
        for (int i = 0; i < nw; i++) s = fmaxf(s, mbuf[i]);
        mbuf[8] = s;
    }
    __syncthreads();
    return mbuf[8];
}

// ---------------- K1: split-K Gram partials ----------------
// grid (4,4,16): x,y = 64x64 tile; z = mat*8 + split. block = 256 threads.
__global__ void __launch_bounds__(256) gram_kernel(
        const float* __restrict__ sq, const float* __restrict__ sp,
        const float* __restrict__ tq, const float* __restrict__ tp) {
    int mat = blockIdx.z >> 3;
    int split = blockIdx.z & 7;
    const float* q = mat ? tq : sq;
    const float* p = mat ? tp : sp;
    float* Gp = g_Gp[mat][split];

    __shared__ float As[TSTEP][68];   // k-major
    __shared__ float Bs[TSTEP][68];

    int TI = blockIdx.x * 64;
    int TK = blockIdx.y * 64;
    int tid = threadIdx.x;
    int tx = tid & 15, ty = tid >> 4;
    int lr = tid >> 2;
    int lc = (tid & 3) * 4;

    float acc[4][4];
    #pragma unroll
    for (int a = 0; a < 4; a++)
        #pragma unroll
        for (int b = 0; b < 4; b++) acc[a][b] = 0.0f;

    int k0base = split * CHUNK;
    #pragma unroll 1
    for (int s = 0; s < CHUNK / TSTEP; s++) {
        int k0 = k0base + s * TSTEP;
        float4 av = *(const float4*)(row_ptr(q, p, TI + lr) + k0 + lc);
        float4 bv = *(const float4*)(row_ptr(q, p, TK + lr) + k0 + lc);
        As[lc + 0][lr] = av.x; As[lc + 1][lr] = av.y;
        As[lc + 2][lr] = av.z; As[lc + 3][lr] = av.w;
        Bs[lc + 0][lr] = bv.x; Bs[lc + 1][lr] = bv.y;
        Bs[lc + 2][lr] = bv.z; Bs[lc + 3][lr] = bv.w;
        __syncthreads();
        #pragma unroll
        for (int kk = 0; kk < TSTEP; kk++) {
            float4 a = *(const float4*)&As[kk][ty * 4];
            float4 b = *(const float4*)&Bs[kk][tx * 4];
            acc[0][0] = fmaf(a.x, b.x, acc[0][0]);
            acc[0][1] = fmaf(a.x, b.y, acc[0][1]);
            acc[0][2] = fmaf(a.x, b.z, acc[0][2]);
            acc[0][3] = fmaf(a.x, b.w, acc[0][3]);
            acc[1][0] = fmaf(a.y, b.x, acc[1][0]);
            acc[1][1] = fmaf(a.y, b.y, acc[1][1]);
            acc[1][2] = fmaf(a.y, b.z, acc[1][2]);
            acc[1][3] = fmaf(a.y, b.w, acc[1][3]);
            acc[2][0] = fmaf(a.z, b.x, acc[2][0]);
            acc[2][1] = fmaf(a.z, b.y, acc[2][1]);
            acc[2][2] = fmaf(a.z, b.z, acc[2][2]);
            acc[2][3] = fmaf(a.z, b.w, acc[2][3]);
            acc[3][0] = fmaf(a.w, b.x, acc[3][0]);
            acc[3][1] = fmaf(a.w, b.y, acc[3][1]);
            acc[3][2] = fmaf(a.w, b.z, acc[3][2]);
            acc[3][3] = fmaf(a.w, b.w, acc[3][3]);
        }
        __syncthreads();
    }

    #pragma unroll
    for (int r = 0; r < 4; r++) {
        float4 v = make_float4(acc[r][0], acc[r][1], acc[r][2], acc[r][3]);
        *(float4*)&Gp[(TI + ty * 4 + r) * N + TK + tx * 4] = v;
    }
}

// ---------------- K2: fold split-K, diag + row sums; ticket block -> means ----------------
// grid (N, 2), block 256.
__global__ void __launch_bounds__(256) reduce_kernel() {
    int i = blockIdx.x, z = blockIdx.y, t = threadIdx.x;
    float s = 0.0f;
    #pragma unroll
    for (int pp = 0; pp < SPLITK; pp++) s += g_Gp[z][pp][i * N + t];
    (z ? g_Gt : g_Gs)[i * N + t] = s;
    if (t == i) (z ? g_n2t : g_n2s)[i] = s;
    float rsum = block_sum_all(s);
    if (t == 0) g_rowsum[z][i] = rsum;

    __shared__ unsigned int stick;
    __threadfence();
    if (t == 0) stick = atomicAdd(&g_ctr1, 1);
    __syncthreads();
    if (stick == 2 * N - 1) {
        // triu ds sum = N*tr(G) - sum(G)
        float tr_s  = block_sum_all(g_n2s[t]);
        float tr_t  = block_sum_all(g_n2t[t]);
        float sum_s = block_sum_all(g_rowsum[0][t]);
        float sum_t = block_sum_all(g_rowsum[1][t]);
        if (t == 0) {
            g_invm[0] = 1.0f / (((float)N * tr_s - sum_s) / CNT2 + EPSF);
            g_invm[1] = 1.0f / (((float)N * tr_t - sum_t) / CNT2 + EPSF);
            g_ctr1 = 0;   // reset for next graph replay
        }
    }
}

// ---------------- K3: fused angle + dist + contrastive; ticket block -> output ----------------
// grid 512: bid = jquad*8 + q. Block handles 4 j's (jbase..jbase+3), i-comb q (step 8).
// cos(i,k at vertex j) = r_jk * ( r_ji*(g_ik - g_jk) + p_i ),  p_i = (g_jj - g_ji)*r_ji
// r row diagonal zeroed => i==j, k==j terms exactly 0; (i,k) symmetric => i>k only.
__global__ void __launch_bounds__(256) fused_kernel(float* __restrict__ out, int out_size) {
    int bid = blockIdx.x;
    int jquad = bid >> 3;
    int q = bid & 7;
    int jbase = jquad * 4;
    int k = threadIdx.x;

    __shared__ float n2s_sh[N], n2t_sh[N];
    __shared__ float gsj_sh[4][N], gtj_sh[4][N];
    __shared__ float4 sp_sh[4][N];   // {rs, ps, rt, pt} per (jj, i)

    float n2sk = g_n2s[k], n2tk = g_n2t[k];
    n2s_sh[k] = n2sk; n2t_sh[k] = n2tk;
    float gsv[4], gtv[4];
    #pragma unroll
    for (int jj = 0; jj < 4; jj++) {
        gsv[jj] = g_Gs[(jbase + jj) * N + k];
        gtv[jj] = g_Gt[(jbase + jj) * N + k];
        gsj_sh[jj][k] = gsv[jj];
        gtj_sh[jj][k] = gtv[jj];
    }
    __syncthreads();

    float rsk[4], rtk[4];
    #pragma unroll
    for (int jj = 0; jj < 4; jj++) {
        int j = jbase + jj;
        float ds = n2s_sh[j] + n2sk - 2.0f * gsv[jj];
        float dt = n2t_sh[j] + n2tk - 2.0f * gtv[jj];
        float rs = (k == j) ? 0.0f : 1.0f / (sqrtf(fmaxf(ds, 0.0f)) + EPSF);
        float rt = (k == j) ? 0.0f : 1.0f / (sqrtf(fmaxf(dt, 0.0f)) + EPSF);
        rsk[jj] = rs; rtk[jj] = rt;
        sp_sh[jj][k] = make_float4(rs, (n2s_sh[j] - gsv[jj]) * rs,
                                   rt, (n2t_sh[j] - gtv[jj]) * rt);
    }
    __syncthreads();

    // ---- dist huber + contrastive for j = jbase + q (q < 4 only; block-uniform) ----
    if (q < 4) {
        int j = jbase + q;
        float gs = gsj_sh[q][k], gt = gtj_sh[q][k];
        float ds = n2s_sh[j] + n2sk - 2.0f * gs;
        float dt = n2t_sh[j] + n2tk - 2.0f * gt;
        float v = 0.0f;
        if (k > j) {
            float diff = ds * g_invm[0] - dt * g_invm[1];
            float a = fabsf(diff), m = fminf(a, 1.0f);
            v = 0.5f * m * (2.0f * a - m);
        }
        float sd = block_sum_all(v);
        if (k == 0) g_pdist[j] = sd;
        if (j < BH) {
            float sval = (k < BH) ? gsj_sh[q][BH + k] : -INFINITY;
            float mx = block_max_all(sval);
            float ex = (k < BH) ? expf(INV_TEMP * (sval - mx)) : 0.0f;
            float sm = block_sum_all(ex);
            if (k == 0)
                g_pcl[j] = INV_TEMP * mx + logf(sm) - INV_TEMP * gsj_sh[q][BH + j];
        }
    }

    // ---- angle loop: i > k (pair symmetry), comb q of 8, warp-uniform base ----
    const float* __restrict__ Gsk = g_Gs + k;   // column k (stride N)
    const float* __restrict__ Gtk = g_Gt + k;
    int wbase = k & ~31;
    float acc = 0.0f;
    #pragma unroll 4
    for (int i = wbase + 1 + q; i < N; i += 8) {
        float gsik = Gsk[i * N];
        float gtik = Gtk[i * N];
        float pred = (i > k) ? 1.0f : 0.0f;
        float hsum = 0.0f;
        #pragma unroll
        for (int jj = 0; jj < 4; jj++) {
            float4 c = sp_sh[jj][i];
            float us = fmaf(c.x, gsik - gsv[jj], c.y);
            float ut = fmaf(c.z, gtik - gtv[jj], c.w);
            float d  = fmaf(rtk[jj], -ut, rsk[jj] * us);  // cos_s - cos_t
            float a  = fabsf(d);
            float m  = fminf(a, 1.0f);
            hsum += m * fmaf(2.0f, a, -m);                // 2*huber
        }
        acc = fmaf(pred, hsum, acc);
    }
    // sum_{i>k} 2*huber == sum_{i!=k} huber
    float sa = block_sum_all(acc);
    if (k == 0) g_pang[bid] = sa;

    // ---- ticket: last block combines everything and writes output ----
    __shared__ unsigned int stick;
    __threadfence();
    if (k == 0) stick = atomicAdd(&g_ctr2, 1);
    __syncthreads();
    if (stick == NFB - 1) {
        __threadfence();
        float dsum  = block_sum_all(g_pdist[k]);
        float asum  = block_sum_all(g_pang[k] + g_pang[k + 256]);
        float clsum = block_sum_all((k < BH) ? g_pcl[k] : 0.0f);
        if (k == 0) {
            float contrastive = clsum / (float)BH;
            float kd = 0.5f * (dsum / CNT2) + 0.5f * (asum / CNT3);
            if (out_size > 0) out[0] = contrastive + kd;
            if (out_size > 1) out[1] = contrastive;
            if (out_size > 2) out[2] = kd;
            g_ctr2 = 0;   // reset for next graph replay
        }
    }
}

// ---------------- launch ----------------
extern "C" void kernel_launch(void* const* d_in, const int* in_sizes, int n_in,
                              void* d_out, int out_size) {
    const float* sq = (const float*)d_in[0];
    const float* sp = (const float*)d_in[1];
    const float* tq = (const float*)d_in[2];
    const float* tp = (const float*)d_in[3];
    float* out = (float*)d_out;

    gram_kernel<<<dim3(4, 4, 16), 256>>>(sq, sp, tq, tp);
    reduce_kernel<<<dim3(N, 2), 256>>>();
    fused_kernel<<<NFB, 256>>>(out, out_size);
}

// round 10
// speedup vs baseline: 2.8999x; 1.0077x over previous
#include <cuda_runtime.h>
#include <math.h>

#define N 256            // 2B
#define BH 128           // B
#define D 768
#define EPSF 1e-8f
#define INV_TEMP 20.0f   // 1/0.05
#define CNT2 32640.0f    // N(N-1)/2
#define CNT3 16581120.0f // N(N-1)(N-2)

#define SPLITK 16
#define CHUNK 48         // D / SPLITK
#define TSTEP 16         // k per smem stage

#define NFB 512          // fused grid: 64 j-quads x 8 i-combs

// ---------------- scratch (device globals; no allocation) ----------------
__device__ float g_Gp[2][SPLITK][N * N];  // split-K partials (8 MB)
__device__ float g_Gs[N * N];
__device__ float g_Gt[N * N];
__device__ float g_n2s[N];       // diag of Gs (row squared norms)
__device__ float g_n2t[N];
__device__ float g_rowsum[2][N]; // per-row sums of G
__device__ float g_invm[2];      // 1/mean_sd, 1/mean_td
__device__ float g_pang[NFB];    // per-fused-block angle partials
__device__ float g_pdist[N];     // per-j distance-huber partials
__device__ float g_pcl[BH];      // per-row contrastive loss
__device__ unsigned int g_ctr1 = 0;  // reduce ticket
__device__ unsigned int g_ctr2 = 0;  // fused ticket

// ---------------- helpers ----------------
__device__ __forceinline__ const float* row_ptr(const float* q, const float* p, int r) {
    return (r < BH) ? (q + r * D) : (p + (r - BH) * D);
}

// block-wide sum, EXPLICIT linear tid/count; result broadcast to all threads.
__device__ __forceinline__ float block_sum_tid(float v, int tid, int nthreads) {
    __shared__ float sbuf[9];
    __syncthreads();                       // protect sbuf reuse across calls
    #pragma unroll
    for (int o = 16; o > 0; o >>= 1) v += __shfl_down_sync(0xffffffffu, v, o);
    int w = tid >> 5, l = tid & 31;
    if (l == 0) sbuf[w] = v;
    __syncthreads();
    if (tid == 0) {
        float s = 0.0f;
        int nw = nthreads >> 5;
        for (int i = 0; i < nw; i++) s += sbuf[i];
        sbuf[8] = s;
    }
    __syncthreads();
    return sbuf[8];
}

__device__ __forceinline__ float block_sum_all(float v) {
    return block_sum_tid(v, threadIdx.x, blockDim.x);
}

// block-wide max, result broadcast (1-D blocks only).
__device__ __forceinline__ float block_max_all(float v) {
    __shared__ float mbuf[9];
    __syncthreads();
    #pragma unroll
    for (int o = 16; o > 0; o >>= 1) v = fmaxf(v, __shfl_down_sync(0xffffffffu, v, o));
    int w = threadIdx.x >> 5, l = threadIdx.x & 31;
    if (l == 0) mbuf[w] = v;
    __syncthreads();
    if (threadIdx.x == 0) {
        float s = -INFINITY;
        int nw = blockDim.x >> 5;
        for (int i = 0; i < nw; i++) s = fmaxf(s, mbuf[i]);
        mbuf[8] = s;
    }
    __syncthreads();
    return mbuf[8];
}

// ---------------- K1: split-K Gram partials ----------------
// grid (4,4,32): x,y = 64x64 tile; z = mat*16 + split. block = 256 threads.
__global__ void __launch_bounds__(256) gram_kernel(
        const float* __restrict__ sq, const float* __restrict__ sp,
        const float* __restrict__ tq, const float* __restrict__ tp) {
    int mat = blockIdx.z >> 4;
    int split = blockIdx.z & 15;
    const float* q = mat ? tq : sq;
    const float* p = mat ? tp : sp;
    float* Gp = g_Gp[mat][split];

    __shared__ float As[TSTEP][68];   // k-major
    __shared__ float Bs[TSTEP][68];

    int TI = blockIdx.x * 64;
    int TK = blockIdx.y * 64;
    int tid = threadIdx.x;
    int tx = tid & 15, ty = tid >> 4;
    int lr = tid >> 2;
    int lc = (tid & 3) * 4;

    float acc[4][4];
    #pragma unroll
    for (int a = 0; a < 4; a++)
        #pragma unroll
        for (int b = 0; b < 4; b++) acc[a][b] = 0.0f;

    int k0base = split * CHUNK;
    #pragma unroll 1
    for (int s = 0; s < CHUNK / TSTEP; s++) {
        int k0 = k0base + s * TSTEP;
        float4 av = *(const float4*)(row_ptr(q, p, TI + lr) + k0 + lc);
        float4 bv = *(const float4*)(row_ptr(q, p, TK + lr) + k0 + lc);
        As[lc + 0][lr] = av.x; As[lc + 1][lr] = av.y;
        As[lc + 2][lr] = av.z; As[lc + 3][lr] = av.w;
        Bs[lc + 0][lr] = bv.x; Bs[lc + 1][lr] = bv.y;
        Bs[lc + 2][lr] = bv.z; Bs[lc + 3][lr] = bv.w;
        __syncthreads();
        #pragma unroll
        for (int kk = 0; kk < TSTEP; kk++) {
            float4 a = *(const float4*)&As[kk][ty * 4];
            float4 b = *(const float4*)&Bs[kk][tx * 4];
            acc[0][0] = fmaf(a.x, b.x, acc[0][0]);
            acc[0][1] = fmaf(a.x, b.y, acc[0][1]);
            acc[0][2] = fmaf(a.x, b.z, acc[0][2]);
            acc[0][3] = fmaf(a.x, b.w, acc[0][3]);
            acc[1][0] = fmaf(a.y, b.x, acc[1][0]);
            acc[1][1] = fmaf(a.y, b.y, acc[1][1]);
            acc[1][2] = fmaf(a.y, b.z, acc[1][2]);
            acc[1][3] = fmaf(a.y, b.w, acc[1][3]);
            acc[2][0] = fmaf(a.z, b.x, acc[2][0]);
            acc[2][1] = fmaf(a.z, b.y, acc[2][1]);
            acc[2][2] = fmaf(a.z, b.z, acc[2][2]);
            acc[2][3] = fmaf(a.z, b.w, acc[2][3]);
            acc[3][0] = fmaf(a.w, b.x, acc[3][0]);
            acc[3][1] = fmaf(a.w, b.y, acc[3][1]);
            acc[3][2] = fmaf(a.w, b.z, acc[3][2]);
            acc[3][3] = fmaf(a.w, b.w, acc[3][3]);
        }
        __syncthreads();
    }

    #pragma unroll
    for (int r = 0; r < 4; r++) {
        float4 v = make_float4(acc[r][0], acc[r][1], acc[r][2], acc[r][3]);
        *(float4*)&Gp[(TI + ty * 4 + r) * N + TK + tx * 4] = v;
    }
}

// ---------------- K2: fold split-K, diag + row sums; ticket block -> means ----------------
// grid (N, 2), block 256.
__global__ void __launch_bounds__(256) reduce_kernel() {
    int i = blockIdx.x, z = blockIdx.y, t = threadIdx.x;
    float s = 0.0f;
    #pragma unroll
    for (int pp = 0; pp < SPLITK; pp++) s += g_Gp[z][pp][i * N + t];
    (z ? g_Gt : g_Gs)[i * N + t] = s;
    if (t == i) (z ? g_n2t : g_n2s)[i] = s;
    float rsum = block_sum_all(s);
    if (t == 0) g_rowsum[z][i] = rsum;

    __shared__ unsigned int stick;
    __threadfence();
    if (t == 0) stick = atomicAdd(&g_ctr1, 1);
    __syncthreads();
    if (stick == 2 * N - 1) {
        // triu ds sum = N*tr(G) - sum(G)
        float tr_s  = block_sum_all(g_n2s[t]);
        float tr_t  = block_sum_all(g_n2t[t]);
        float sum_s = block_sum_all(g_rowsum[0][t]);
        float sum_t = block_sum_all(g_rowsum[1][t]);
        if (t == 0) {
            g_invm[0] = 1.0f / (((float)N * tr_s - sum_s) / CNT2 + EPSF);
            g_invm[1] = 1.0f / (((float)N * tr_t - sum_t) / CNT2 + EPSF);
            g_ctr1 = 0;   // reset for next graph replay
        }
    }
}

// ---------------- K3: fused angle + dist + contrastive; ticket block -> output ----------------
// grid 512: bid = jquad*8 + q. Block handles 4 j's (jbase..jbase+3), i-comb q (step 8).
// cos(i,k at vertex j) = r_jk * ( r_ji*(g_ik - g_jk) + p_i ),  p_i = (g_jj - g_ji)*r_ji
// r row diagonal zeroed => i==j, k==j terms exactly 0; (i,k) symmetric => i>k only.
__global__ void __launch_bounds__(256) fused_kernel(float* __restrict__ out, int out_size) {
    int bid = blockIdx.x;
    int jquad = bid >> 3;
    int q = bid & 7;
    int jbase = jquad * 4;
    int k = threadIdx.x;

    __shared__ float n2s_sh[N], n2t_sh[N];
    __shared__ float gsj_sh[4][N], gtj_sh[4][N];
    __shared__ float4 sp_sh[4][N];   // {rs, ps, rt, pt} per (jj, i)

    float n2sk = g_n2s[k], n2tk = g_n2t[k];
    n2s_sh[k] = n2sk; n2t_sh[k] = n2tk;
    float gsv[4], gtv[4];
    #pragma unroll
    for (int jj = 0; jj < 4; jj++) {
        gsv[jj] = g_Gs[(jbase + jj) * N + k];
        gtv[jj] = g_Gt[(jbase + jj) * N + k];
        gsj_sh[jj][k] = gsv[jj];
        gtj_sh[jj][k] = gtv[jj];
    }
    __syncthreads();

    float rsk[4], rtk[4];
    #pragma unroll
    for (int jj = 0; jj < 4; jj++) {
        int j = jbase + jj;
        float ds = n2s_sh[j] + n2sk - 2.0f * gsv[jj];
        float dt = n2t_sh[j] + n2tk - 2.0f * gtv[jj];
        float rs = (k == j) ? 0.0f : 1.0f / (sqrtf(fmaxf(ds, 0.0f)) + EPSF);
        float rt = (k == j) ? 0.0f : 1.0f / (sqrtf(fmaxf(dt, 0.0f)) + EPSF);
        rsk[jj] = rs; rtk[jj] = rt;
        sp_sh[jj][k] = make_float4(rs, (n2s_sh[j] - gsv[jj]) * rs,
                                   rt, (n2t_sh[j] - gtv[jj]) * rt);
    }
    __syncthreads();

    // ---- dist huber + contrastive for j = jbase + q (q < 4 only; block-uniform) ----
    if (q < 4) {
        int j = jbase + q;
        float gs = gsj_sh[q][k], gt = gtj_sh[q][k];
        float ds = n2s_sh[j] + n2sk - 2.0f * gs;
        float dt = n2t_sh[j] + n2tk - 2.0f * gt;
        float v = 0.0f;
        if (k > j) {
            float diff = ds * g_invm[0] - dt * g_invm[1];
            float a = fabsf(diff), m = fminf(a, 1.0f);
            v = 0.5f * m * (2.0f * a - m);
        }
        float sd = block_sum_all(v);
        if (k == 0) g_pdist[j] = sd;
        if (j < BH) {
            float sval = (k < BH) ? gsj_sh[q][BH + k] : -INFINITY;
            float mx = block_max_all(sval);
            float ex = (k < BH) ? expf(INV_TEMP * (sval - mx)) : 0.0f;
            float sm = block_sum_all(ex);
            if (k == 0)
                g_pcl[j] = INV_TEMP * mx + logf(sm) - INV_TEMP * gsj_sh[q][BH + j];
        }
    }

    // ---- angle loop: i > k (pair symmetry), comb q of 8, warp-uniform base ----
    const float* __restrict__ Gsk = g_Gs + k;   // column k (stride N)
    const float* __restrict__ Gtk = g_Gt + k;
    int wbase = k & ~31;
    float acc = 0.0f;
    #pragma unroll 4
    for (int i = wbase + 1 + q; i < N; i += 8) {
        float gsik = Gsk[i * N];
        float gtik = Gtk[i * N];
        float pred = (i > k) ? 1.0f : 0.0f;
        float hsum = 0.0f;
        #pragma unroll
        for (int jj = 0; jj < 4; jj++) {
            float4 c = sp_sh[jj][i];
            float us = fmaf(c.x, gsik - gsv[jj], c.y);
            float ut = fmaf(c.z, gtik - gtv[jj], c.w);
            float d  = fmaf(rtk[jj], -ut, rsk[jj] * us);  // cos_s - cos_t
            float a  = fabsf(d);
            float m  = fminf(a, 1.0f);
            hsum += m * fmaf(2.0f, a, -m);                // 2*huber
        }
        acc = fmaf(pred, hsum, acc);
    }
    // sum_{i>k} 2*huber == sum_{i!=k} huber
    float sa = block_sum_all(acc);
    if (k == 0) g_pang[bid] = sa;

    // ---- ticket: last block combines everything and writes output ----
    __shared__ unsigned int stick;
    __threadfence();
    if (k == 0) stick = atomicAdd(&g_ctr2, 1);
    __syncthreads();
    if (stick == NFB - 1) {
        __threadfence();
        float dsum  = block_sum_all(g_pdist[k]);
        float asum  = block_sum_all(g_pang[k] + g_pang[k + 256]);
        float clsum = block_sum_all((k < BH) ? g_pcl[k] : 0.0f);
        if (k == 0) {
            float contrastive = clsum / (float)BH;
            float kd = 0.5f * (dsum / CNT2) + 0.5f * (asum / CNT3);
            if (out_size > 0) out[0] = contrastive + kd;
            if (out_size > 1) out[1] = contrastive;
            if (out_size > 2) out[2] = kd;
            g_ctr2 = 0;   // reset for next graph replay
        }
    }
}

// ---------------- launch ----------------
extern "C" void kernel_launch(void* const* d_in, const int* in_sizes, int n_in,
                              void* d_out, int out_size) {
    const float* sq = (const float*)d_in[0];
    const float* sp = (const float*)d_in[1];
    const float* tq = (const float*)d_in[2];
    const float* tp = (const float*)d_in[3];
    float* out = (float*)d_out;

    gram_kernel<<<dim3(4, 4, 32), 256>>>(sq, sp, tq, tp);
    reduce_kernel<<<dim3(N, 2), 256>>>();
    fused_kernel<<<NFB, 256>>>(out, out_size);
}

// round 12
// speedup vs baseline: 2.9027x; 1.0010x over previous
#include <cuda_runtime.h>
#include <math.h>

#define N 256            // 2B
#define BH 128           // B
#define D 768
#define EPSF 1e-8f
#define INV_TEMP 20.0f   // 1/0.05
#define CNT2 32640.0f    // N(N-1)/2
#define CNT3 16581120.0f // N(N-1)(N-2)

#define SPLITK 16
#define CHUNK 48         // D / SPLITK
#define TSTEP 16         // k per smem stage
#define NSTAGE (CHUNK / TSTEP)   // 3

#define NTILE 10         // symmetric 4x4 -> 10 tiles (bx <= by)
#define NFB 512          // fused grid: 64 j-quads x 8 i-combs

// ---------------- scratch (device globals; no allocation) ----------------
__device__ float g_Gp[2][SPLITK][N * N];  // split-K partials (8 MB)
__device__ float g_Gs[N * N];
__device__ float g_Gt[N * N];
__device__ float g_n2s[N];       // diag of Gs (row squared norms)
__device__ float g_n2t[N];
__device__ float g_rowsum[2][N]; // per-row sums of G
__device__ float g_invm[2];      // 1/mean_sd, 1/mean_td
__device__ float g_pang[NFB];    // per-fused-block angle partials
__device__ float g_pdist[N];     // per-j distance-huber partials
__device__ float g_pcl[BH];      // per-row contrastive loss
__device__ unsigned int g_ctr1 = 0;  // reduce ticket
__device__ unsigned int g_ctr2 = 0;  // fused ticket

// symmetric tile map (bx <= by)
__device__ const int TBX[NTILE] = {0, 0, 0, 0, 1, 1, 1, 2, 2, 3};
__device__ const int TBY[NTILE] = {0, 1, 2, 3, 1, 2, 3, 2, 3, 3};

// ---------------- helpers ----------------
__device__ __forceinline__ const float* row_ptr(const float* q, const float* p, int r) {
    return (r < BH) ? (q + r * D) : (p + (r - BH) * D);
}

// block-wide sum, EXPLICIT linear tid/count; result broadcast to all threads.
__device__ __forceinline__ float block_sum_tid(float v, int tid, int nthreads) {
    __shared__ float sbuf[9];
    __syncthreads();                       // protect sbuf reuse across calls
    #pragma unroll
    for (int o = 16; o > 0; o >>= 1) v += __shfl_down_sync(0xffffffffu, v, o);
    int w = tid >> 5, l = tid & 31;
    if (l == 0) sbuf[w] = v;
    __syncthreads();
    if (tid == 0) {
        float s = 0.0f;
        int nw = nthreads >> 5;
        for (int i = 0; i < nw; i++) s += sbuf[i];
        sbuf[8] = s;
    }
    __syncthreads();
    return sbuf[8];
}

__device__ __forceinline__ float block_sum_all(float v) {
    return block_sum_tid(v, threadIdx.x, blockDim.x);
}

// block-wide max, result broadcast (1-D blocks only).
__device__ __forceinline__ float block_max_all(float v) {
    __shared__ float mbuf[9];
    __syncthreads();
    #pragma unroll
    for (int o = 16; o > 0; o >>= 1) v = fmaxf(v, __shfl_down_sync(0xffffffffu, v, o));
    int w = threadIdx.x >> 5, l = threadIdx.x & 31;
    if (l == 0) mbuf[w] = v;
    __syncthreads();
    if (threadIdx.x == 0) {
        float s = -INFINITY;
        int nw = blockDim.x >> 5;
        for (int i = 0; i < nw; i++) s = fmaxf(s, mbuf[i]);
        mbuf[8] = s;
    }
    __syncthreads();
    return mbuf[8];
}

// ---------------- K1: split-K Gram partials, symmetric tiles only ----------------
// grid (10, 32): x = tile (bx<=by); y = mat*16 + split. block = 256 threads.
// Off-diagonal tiles are written twice (normal + register-transposed).
__global__ void __launch_bounds__(256) gram_kernel(
        const float* __restrict__ sq, const float* __restrict__ sp,
        const float* __restrict__ tq, const float* __restrict__ tp) {
    int mat = blockIdx.y >> 4;
    int split = blockIdx.y & 15;
    const float* q = mat ? tq : sq;
    const float* p = mat ? tp : sp;
    float* Gp = g_Gp[mat][split];

    __shared__ float As[TSTEP][68];   // k-major
    __shared__ float Bs[TSTEP][68];

    int bx = TBX[blockIdx.x], by = TBY[blockIdx.x];
    int TI = bx * 64;
    int TK = by * 64;
    int tid = threadIdx.x;
    int tx = tid & 15, ty = tid >> 4;
    int lr = tid >> 2;
    int lc = (tid & 3) * 4;

    float acc[4][4];
    #pragma unroll
    for (int a = 0; a < 4; a++)
        #pragma unroll
        for (int b = 0; b < 4; b++) acc[a][b] = 0.0f;

    int k0base = split * CHUNK;
    const float* arow = row_ptr(q, p, TI + lr) + lc;
    const float* brow = row_ptr(q, p, TK + lr) + lc;

    float4 av = *(const float4*)(arow + k0base);
    float4 bv = *(const float4*)(brow + k0base);

    #pragma unroll
    for (int s = 0; s < NSTAGE; s++) {
        As[lc + 0][lr] = av.x; As[lc + 1][lr] = av.y;
        As[lc + 2][lr] = av.z; As[lc + 3][lr] = av.w;
        Bs[lc + 0][lr] = bv.x; Bs[lc + 1][lr] = bv.y;
        Bs[lc + 2][lr] = bv.z; Bs[lc + 3][lr] = bv.w;
        __syncthreads();
        // prefetch next stage while computing this one
        if (s + 1 < NSTAGE) {
            av = *(const float4*)(arow + k0base + (s + 1) * TSTEP);
            bv = *(const float4*)(brow + k0base + (s + 1) * TSTEP);
        }
        #pragma unroll
        for (int kk = 0; kk < TSTEP; kk++) {
            float4 a = *(const float4*)&As[kk][ty * 4];
            float4 b = *(const float4*)&Bs[kk][tx * 4];
            acc[0][0] = fmaf(a.x, b.x, acc[0][0]);
            acc[0][1] = fmaf(a.x, b.y, acc[0][1]);
            acc[0][2] = fmaf(a.x, b.z, acc[0][2]);
            acc[0][3] = fmaf(a.x, b.w, acc[0][3]);
            acc[1][0] = fmaf(a.y, b.x, acc[1][0]);
            acc[1][1] = fmaf(a.y, b.y, acc[1][1]);
            acc[1][2] = fmaf(a.y, b.z, acc[1][2]);
            acc[1][3] = fmaf(a.y, b.w, acc[1][3]);
            acc[2][0] = fmaf(a.z, b.x, acc[2][0]);
            acc[2][1] = fmaf(a.z, b.y, acc[2][1]);
            acc[2][2] = fmaf(a.z, b.z, acc[2][2]);
            acc[2][3] = fmaf(a.z, b.w, acc[2][3]);
            acc[3][0] = fmaf(a.w, b.x, acc[3][0]);
            acc[3][1] = fmaf(a.w, b.y, acc[3][1]);
            acc[3][2] = fmaf(a.w, b.z, acc[3][2]);
            acc[3][3] = fmaf(a.w, b.w, acc[3][3]);
        }
        __syncthreads();
    }

    // normal tile write: row TI+ty*4+r, cols TK+tx*4..+3
    #pragma unroll
    for (int r = 0; r < 4; r++) {
        float4 v = make_float4(acc[r][0], acc[r][1], acc[r][2], acc[r][3]);
        *(float4*)&Gp[(TI + ty * 4 + r) * N + TK + tx * 4] = v;
    }
    // transposed tile write for off-diagonal tiles:
    // G[TK+tx*4+c][TI+ty*4+r] = acc[r][c] -> contiguous float4 over r
    if (bx != by) {
        #pragma unroll
        for (int c = 0; c < 4; c++) {
            float4 v = make_float4(acc[0][c], acc[1][c], acc[2][c], acc[3][c]);
            *(float4*)&Gp[(TK + tx * 4 + c) * N + TI + ty * 4] = v;
        }
    }
}

// ---------------- K2: fold split-K, diag + row sums; ticket block -> means ----------------
// grid (N, 2), block 256.
__global__ void __launch_bounds__(256) reduce_kernel() {
    int i = blockIdx.x, z = blockIdx.y, t = threadIdx.x;
    float s = 0.0f;
    #pragma unroll
    for (int pp = 0; pp < SPLITK; pp++) s += g_Gp[z][pp][i * N + t];
    (z ? g_Gt : g_Gs)[i * N + t] = s;
    if (t == i) (z ? g_n2t : g_n2s)[i] = s;
    float rsum = block_sum_all(s);
    if (t == 0) g_rowsum[z][i] = rsum;

    __shared__ unsigned int stick;
    __threadfence();
    if (t == 0) stick = atomicAdd(&g_ctr1, 1);
    __syncthreads();
    if (stick == 2 * N - 1) {
        // triu ds sum = N*tr(G) - sum(G)
        float tr_s  = block_sum_all(g_n2s[t]);
        float tr_t  = block_sum_all(g_n2t[t]);
        float sum_s = block_sum_all(g_rowsum[0][t]);
        float sum_t = block_sum_all(g_rowsum[1][t]);
        if (t == 0) {
            g_invm[0] = 1.0f / (((float)N * tr_s - sum_s) / CNT2 + EPSF);
            g_invm[1] = 1.0f / (((float)N * tr_t - sum_t) / CNT2 + EPSF);
            g_ctr1 = 0;   // reset for next graph replay
        }
    }
}

// ---------------- K3: fused angle + dist + contrastive; ticket block -> output ----------------
// grid 512: bid = jquad*8 + q. Block handles 4 j's (jbase..jbase+3), i-comb q (step 8).
// cos(i,k at vertex j) = r_jk * ( r_ji*(g_ik - g_jk) + p_i ),  p_i = (g_jj - g_ji)*r_ji
// r row diagonal zeroed => i==j, k==j terms exactly 0; (i,k) symmetric => i>k only.
__global__ void __launch_bounds__(256) fused_kernel(float* __restrict__ out, int out_size) {
    int bid = blockIdx.x;
    int jquad = bid >> 3;
    int q = bid & 7;
    int jbase = jquad * 4;
    int k = threadIdx.x;

    __shared__ float n2s_sh[N], n2t_sh[N];
    __shared__ float gsj_sh[4][N], gtj_sh[4][N];
    __shared__ float4 sp_sh[4][N];   // {rs, ps, rt, pt} per (jj, i)

    float n2sk = g_n2s[k], n2tk = g_n2t[k];
    n2s_sh[k] = n2sk; n2t_sh[k] = n2tk;
    float gsv[4], gtv[4];
    #pragma unroll
    for (int jj = 0; jj < 4; jj++) {
        gsv[jj] = g_Gs[(jbase + jj) * N + k];
        gtv[jj] = g_Gt[(jbase + jj) * N + k];
        gsj_sh[jj][k] = gsv[jj];
        gtj_sh[jj][k] = gtv[jj];
    }
    __syncthreads();

    float rsk[4], rtk[4];
    #pragma unroll
    for (int jj = 0; jj < 4; jj++) {
        int j = jbase + jj;
        float ds = n2s_sh[j] + n2sk - 2.0f * gsv[jj];
        float dt = n2t_sh[j] + n2tk - 2.0f * gtv[jj];
        float rs = (k == j) ? 0.0f : 1.0f / (sqrtf(fmaxf(ds, 0.0f)) + EPSF);
        float rt = (k == j) ? 0.0f : 1.0f / (sqrtf(fmaxf(dt, 0.0f)) + EPSF);
        rsk[jj] = rs; rtk[jj] = rt;
        sp_sh[jj][k] = make_float4(rs, (n2s_sh[j] - gsv[jj]) * rs,
                                   rt, (n2t_sh[j] - gtv[jj]) * rt);
    }
    __syncthreads();

    // ---- dist huber + contrastive for j = jbase + q (q < 4 only; block-uniform) ----
    if (q < 4) {
        int j = jbase + q;
        float gs = gsj_sh[q][k], gt = gtj_sh[q][k];
        float ds = n2s_sh[j] + n2sk - 2.0f * gs;
        float dt = n2t_sh[j] + n2tk - 2.0f * gt;
        float v = 0.0f;
        if (k > j) {
            float diff = ds * g_invm[0] - dt * g_invm[1];
            float a = fabsf(diff), m = fminf(a, 1.0f);
            v = 0.5f * m * (2.0f * a - m);
        }
        float sd = block_sum_all(v);
        if (k == 0) g_pdist[j] = sd;
        if (j < BH) {
            float sval = (k < BH) ? gsj_sh[q][BH + k] : -INFINITY;
            float mx = block_max_all(sval);
            float ex = (k < BH) ? expf(INV_TEMP * (sval - mx)) : 0.0f;
            float sm = block_sum_all(ex);
            if (k == 0)
                g_pcl[j] = INV_TEMP * mx + logf(sm) - INV_TEMP * gsj_sh[q][BH + j];
        }
    }

    // ---- angle loop: i > k (pair symmetry), comb q of 8, warp-uniform base ----
    const float* __restrict__ Gsk = g_Gs + k;   // column k (stride N)
    const float* __restrict__ Gtk = g_Gt + k;
    int wbase = k & ~31;
    float acc = 0.0f;
    #pragma unroll 4
    for (int i = wbase + 1 + q; i < N; i += 8) {
        float gsik = Gsk[i * N];
        float gtik = Gtk[i * N];
        float pred = (i > k) ? 1.0f : 0.0f;
        float hsum = 0.0f;
        #pragma unroll
        for (int jj = 0; jj < 4; jj++) {
            float4 c = sp_sh[jj][i];
            float us = fmaf(c.x, gsik - gsv[jj], c.y);
            float ut = fmaf(c.z, gtik - gtv[jj], c.w);
            float d  = fmaf(rtk[jj], -ut, rsk[jj] * us);  // cos_s - cos_t
            float a  = fabsf(d);
            float m  = fminf(a, 1.0f);
            hsum += m * fmaf(2.0f, a, -m);                // 2*huber
        }
        acc = fmaf(pred, hsum, acc);
    }
    // sum_{i>k} 2*huber == sum_{i!=k} huber
    float sa = block_sum_all(acc);
    if (k == 0) g_pang[bid] = sa;

    // ---- ticket: last block combines everything and writes output ----
    __shared__ unsigned int stick;
    __threadfence();
    if (k == 0) stick = atomicAdd(&g_ctr2, 1);
    __syncthreads();
    if (stick == NFB - 1) {
        __threadfence();
        float dsum  = block_sum_all(g_pdist[k]);
        float asum  = block_sum_all(g_pang[k] + g_pang[k + 256]);
        float clsum = block_sum_all((k < BH) ? g_pcl[k] : 0.0f);
        if (k == 0) {
            float contrastive = clsum / (float)BH;
            float kd = 0.5f * (dsum / CNT2) + 0.5f * (asum / CNT3);
            if (out_size > 0) out[0] = contrastive + kd;
            if (out_size > 1) out[1] = contrastive;
            if (out_size > 2) out[2] = kd;
            g_ctr2 = 0;   // reset for next graph replay
        }
    }
}

// ---------------- launch ----------------
extern "C" void kernel_launch(void* const* d_in, const int* in_sizes, int n_in,
                              void* d_out, int out_size) {
    const float* sq = (const float*)d_in[0];
    const float* sp = (const float*)d_in[1];
    const float* tq = (const float*)d_in[2];
    const float* tp = (const float*)d_in[3];
    float* out = (float*)d_out;

    gram_kernel<<<dim3(NTILE, 32), 256>>>(sq, sp, tq, tp);
    reduce_kernel<<<dim3(N, 2), 256>>>();
    fused_kernel<<<NFB, 256>>>(out, out_size);
}